// round 3
// baseline (speedup 1.0000x reference)
#include <cuda_runtime.h>
#include <cstdint>

// Problem constants (z: (64,13,128,128) fp32)
#define BB 64
#define CC 13
#define HH 128
#define WW 128
#define HWSZ (HH*WW)                  // 16384
#define NPIX (BB*HWSZ)                // 1,048,576
#define NTOT (CC*NPIX)                // 13,631,488

#define THREADS 256
#define VEC 4
#define NBLOCKS (NPIX / (THREADS*VEC))  // 1024
#define NACC 15                          // commit, ent, 13 channel p0 sums

// Deterministic scratch: per-block partials, fully overwritten every launch.
__device__ float g_partials[NBLOCKS * 16];
// Self-resetting ticket: atomicInc wraps to 0 after NBLOCKS increments,
// so it is 0 again at the start of every graph replay.
__device__ unsigned int g_ticket;

__device__ __forceinline__ void proc_lane(float zv, float& q, float& commit_acc,
                                          float& ent_acc, float& p0_acc, int& idx) {
    bool pos = zv > 0.0f;
    q = pos ? 1.0f : -1.0f;
    float az = fabsf(zv);
    float d = 1.0f - az;
    commit_acc = fmaf(d, d, commit_acc);
    float a = 4.0f * az;                 // |l0 - l1|
    float e = __expf(-a);                // e^{-a} in (0,1]
    float r = __fdividef(1.0f, 1.0f + e);
    float p_big = r;                     // sigmoid(a)
    float p_small = e * r;               // 1 - sigmoid(a)
    float L = __logf(1.0f + e);          // log(1+e)
    ent_acc += fmaf(a, p_small, L);      // H(p) = L + a*(1-sigmoid(a))
    p0_acc += pos ? p_big : p_small;     // p0 = sigmoid(4z)
    idx = (idx << 1) | (pos ? 1 : 0);    // MSB = channel 0
}

__global__ void __launch_bounds__(THREADS)
lfq_fused(const float* __restrict__ z, float* __restrict__ out) {
    float* zq      = out;                 // [0, NTOT)
    float* idx_out = out + NTOT + 2;      // 8B-aligned only -> float2 stores

    int tid = threadIdx.x;
    int g   = blockIdx.x * THREADS + tid;     // group of 4 pixels
    int pix = g * VEC;
    int b   = pix / HWSZ;
    int hw  = pix - b * HWSZ;                 // block never straddles a batch
    size_t base = (size_t)b * (CC * HWSZ) + hw;

    float commit_acc = 0.0f, ent_acc = 0.0f;
    float ch_acc[CC];
    int idx0 = 0, idx1 = 0, idx2 = 0, idx3 = 0;

    #pragma unroll
    for (int c = 0; c < CC; c++) {
        float4 zv = *reinterpret_cast<const float4*>(z + base + (size_t)c * HWSZ);
        float4 qv;
        float ca = 0.0f;
        proc_lane(zv.x, qv.x, commit_acc, ent_acc, ca, idx0);
        proc_lane(zv.y, qv.y, commit_acc, ent_acc, ca, idx1);
        proc_lane(zv.z, qv.z, commit_acc, ent_acc, ca, idx2);
        proc_lane(zv.w, qv.w, commit_acc, ent_acc, ca, idx3);
        *reinterpret_cast<float4*>(zq + base + (size_t)c * HWSZ) = qv;
        ch_acc[c] = ca;
    }

    *reinterpret_cast<float2*>(idx_out + pix)     = make_float2((float)idx0, (float)idx1);
    *reinterpret_cast<float2*>(idx_out + pix + 2) = make_float2((float)idx2, (float)idx3);

    // ---- block reduction of 15 accumulators ----
    float vals[NACC];
    vals[0] = commit_acc;
    vals[1] = ent_acc;
    #pragma unroll
    for (int c = 0; c < CC; c++) vals[2 + c] = ch_acc[c];

    #pragma unroll
    for (int i = 0; i < NACC; i++) {
        #pragma unroll
        for (int o = 16; o; o >>= 1)
            vals[i] += __shfl_xor_sync(0xffffffffu, vals[i], o);
    }

    __shared__ float s[NACC];
    if (tid < NACC) s[tid] = 0.0f;
    __syncthreads();
    if ((tid & 31) == 0) {
        #pragma unroll
        for (int i = 0; i < NACC; i++) atomicAdd(&s[i], vals[i]);
    }
    __syncthreads();
    if (tid < NACC) g_partials[blockIdx.x * 16 + tid] = s[tid];

    // ---- last-block-done finalize ----
    __shared__ bool is_last;
    __threadfence();                         // publish partials
    if (tid == 0) {
        unsigned int old = atomicInc(&g_ticket, NBLOCKS - 1);  // wraps to 0
        is_last = (old == NBLOCKS - 1);
    }
    __syncthreads();
    if (!is_last) return;

    __threadfence();                         // acquire all partials

    float acc[NACC];
    #pragma unroll
    for (int i = 0; i < NACC; i++) acc[i] = 0.0f;
    for (int r = tid; r < NBLOCKS; r += THREADS) {
        const float* row = &g_partials[r * 16];
        #pragma unroll
        for (int i = 0; i < NACC; i++) acc[i] += row[i];
    }
    #pragma unroll
    for (int i = 0; i < NACC; i++) {
        #pragma unroll
        for (int o = 16; o; o >>= 1)
            acc[i] += __shfl_xor_sync(0xffffffffu, acc[i], o);
    }

    if (tid < NACC) s[tid] = 0.0f;
    __syncthreads();
    if ((tid & 31) == 0) {
        #pragma unroll
        for (int i = 0; i < NACC; i++) atomicAdd(&s[i], acc[i]);
    }
    __syncthreads();

    if (tid == 0) {
        double commit = (double)s[0] / (double)NTOT * 1.25 * 0.1;
        double entropy = (double)s[1] / (double)NTOT;
        double mean_ent = 0.0;
        for (int c = 0; c < CC; c++) {
            double mp = (double)s[2 + c] / (double)NPIX;
            if (mp < 1e-12) mp = 1e-12;
            if (mp > 1.0 - 1e-12) mp = 1.0 - 1e-12;
            mean_ent += -(mp * log(mp) + (1.0 - mp) * log(1.0 - mp));
        }
        mean_ent /= (double)CC;
        out[NTOT]     = (float)commit;
        out[NTOT + 1] = (float)((entropy - mean_ent) * 0.1);
    }
}

extern "C" void kernel_launch(void* const* d_in, const int* in_sizes, int n_in,
                              void* d_out, int out_size) {
    const float* z = (const float*)d_in[0];
    float* out = (float*)d_out;
    lfq_fused<<<NBLOCKS, THREADS>>>(z, out);
}

// round 4
// speedup vs baseline: 1.2218x; 1.2218x over previous
#include <cuda_runtime.h>
#include <cstdint>

// Problem constants (z: (64,13,128,128) fp32)
#define BB 64
#define CC 13
#define HH 128
#define WW 128
#define HWSZ (HH*WW)                  // 16384
#define NPIX (BB*HWSZ)                // 1,048,576
#define NTOT (CC*NPIX)                // 13,631,488

#define THREADS 256
#define VEC 4
#define NBLOCKS (NPIX / (THREADS*VEC))  // 1024
#define NACC 15                          // commit, ent, 13 channel p0 sums

// Deterministic scratch: per-block partials, fully overwritten every launch.
__device__ float g_partials[NBLOCKS * 16];

__device__ __forceinline__ void proc_lane(float zv, float& q, float& commit_acc,
                                          float& ent_acc, float& p0_acc, int& idx) {
    bool pos = zv > 0.0f;
    q = pos ? 1.0f : -1.0f;
    float az = fabsf(zv);
    float d = 1.0f - az;
    commit_acc = fmaf(d, d, commit_acc);
    float a = 4.0f * az;                 // |l0 - l1|
    float e = __expf(-a);                // e^{-a} in (0,1]
    float r = __fdividef(1.0f, 1.0f + e);
    float p_big = r;                     // sigmoid(a)
    float p_small = e * r;               // 1 - sigmoid(a)
    float L = __logf(1.0f + e);          // log(1+e)
    ent_acc += fmaf(a, p_small, L);      // H(p)
    p0_acc += pos ? p_big : p_small;     // p0 = sigmoid(4z)
    idx = (idx << 1) | (pos ? 1 : 0);    // MSB = channel 0
}

__device__ __forceinline__ float warp_sum(float v) {
    #pragma unroll
    for (int o = 16; o; o >>= 1) v += __shfl_xor_sync(0xffffffffu, v, o);
    return v;
}

__global__ void __launch_bounds__(THREADS)
lfq_main(const float* __restrict__ z, float* __restrict__ out) {
    float* zq      = out;                 // [0, NTOT)
    float* idx_out = out + NTOT + 2;      // 8B-aligned only -> float2 stores

    __shared__ float s[NACC];
    int tid = threadIdx.x;
    if (tid < NACC) s[tid] = 0.0f;
    __syncthreads();

    int g   = blockIdx.x * THREADS + tid;     // group of 4 pixels
    int pix = g * VEC;
    int b   = pix / HWSZ;
    int hw  = pix - b * HWSZ;                 // block never straddles a batch
    size_t base = (size_t)b * (CC * HWSZ) + hw;

    float commit_acc = 0.0f, ent_acc = 0.0f;
    int idx0 = 0, idx1 = 0, idx2 = 0, idx3 = 0;
    bool lane0 = (tid & 31) == 0;

    // one-ahead prefetch pipeline over channels
    float4 nxt = *reinterpret_cast<const float4*>(z + base);
    #pragma unroll
    for (int c = 0; c < CC; c++) {
        float4 zv = nxt;
        if (c + 1 < CC)
            nxt = *reinterpret_cast<const float4*>(z + base + (size_t)(c + 1) * HWSZ);
        float4 qv;
        float ca = 0.0f;
        proc_lane(zv.x, qv.x, commit_acc, ent_acc, ca, idx0);
        proc_lane(zv.y, qv.y, commit_acc, ent_acc, ca, idx1);
        proc_lane(zv.z, qv.z, commit_acc, ent_acc, ca, idx2);
        proc_lane(zv.w, qv.w, commit_acc, ent_acc, ca, idx3);
        *reinterpret_cast<float4*>(zq + base + (size_t)c * HWSZ) = qv;
        // channel sum -> smem, frees the register immediately
        ca = warp_sum(ca);
        if (lane0) atomicAdd(&s[2 + c], ca);
    }

    *reinterpret_cast<float2*>(idx_out + pix)     = make_float2((float)idx0, (float)idx1);
    *reinterpret_cast<float2*>(idx_out + pix + 2) = make_float2((float)idx2, (float)idx3);

    commit_acc = warp_sum(commit_acc);
    ent_acc    = warp_sum(ent_acc);
    if (lane0) {
        atomicAdd(&s[0], commit_acc);
        atomicAdd(&s[1], ent_acc);
    }
    __syncthreads();
    if (tid < NACC) g_partials[blockIdx.x * 16 + tid] = s[tid];
}

__global__ void __launch_bounds__(THREADS)
lfq_finalize(float* __restrict__ out) {
    int tid = threadIdx.x;
    __shared__ float s[NACC];
    if (tid < NACC) s[tid] = 0.0f;
    __syncthreads();

    float acc[NACC];
    #pragma unroll
    for (int i = 0; i < NACC; i++) acc[i] = 0.0f;
    for (int r = tid; r < NBLOCKS; r += THREADS) {
        const float* row = &g_partials[r * 16];
        #pragma unroll
        for (int i = 0; i < NACC; i++) acc[i] += row[i];
    }
    bool lane0 = (tid & 31) == 0;
    #pragma unroll
    for (int i = 0; i < NACC; i++) {
        float v = acc[i];
        #pragma unroll
        for (int o = 16; o; o >>= 1) v += __shfl_xor_sync(0xffffffffu, v, o);
        if (lane0) atomicAdd(&s[i], v);
    }
    __syncthreads();

    if (tid == 0) {
        double commit = (double)s[0] / (double)NTOT * 1.25 * 0.1;
        double entropy = (double)s[1] / (double)NTOT;
        double mean_ent = 0.0;
        for (int c = 0; c < CC; c++) {
            double mp = (double)s[2 + c] / (double)NPIX;
            if (mp < 1e-12) mp = 1e-12;
            if (mp > 1.0 - 1e-12) mp = 1.0 - 1e-12;
            mean_ent += -(mp * log(mp) + (1.0 - mp) * log(1.0 - mp));
        }
        mean_ent /= (double)CC;
        out[NTOT]     = (float)commit;
        out[NTOT + 1] = (float)((entropy - mean_ent) * 0.1);
    }
}

extern "C" void kernel_launch(void* const* d_in, const int* in_sizes, int n_in,
                              void* d_out, int out_size) {
    const float* z = (const float*)d_in[0];
    float* out = (float*)d_out;
    lfq_main<<<NBLOCKS, THREADS>>>(z, out);
    lfq_finalize<<<1, THREADS>>>(out);
}

// round 5
// speedup vs baseline: 1.4262x; 1.1673x over previous
#include <cuda_runtime.h>
#include <cstdint>

// z: (64,13,128,128) fp32
#define BB 64
#define CC 13
#define HWSZ 16384                       // 128*128
#define NPIX (BB*HWSZ)                   // 1,048,576
#define NTOT (CC*NPIX)                   // 13,631,488
#define NPLANES (BB*CC)                  // 832
#define THREADS 256

// Kernel A: each block = one quarter (4096 floats) of one (b,c) plane.
#define A_BLOCKS (NPLANES*4)             // 3328

// Deterministic scratch (fully overwritten every launch; no runtime allocs).
__device__ float g_partials[A_BLOCKS*4];         // [commit, ent, chsum, pad] per block
__device__ unsigned char g_signs[NTOT/4];        // 4 sign bits per byte, 3.4MB

__device__ __forceinline__ float warp_sum(float v) {
    #pragma unroll
    for (int o = 16; o; o >>= 1) v += __shfl_xor_sync(0xffffffffu, v, o);
    return v;
}

__device__ __forceinline__ void proc(float zv, float& q, float& commit,
                                     float& ent, float& ch, unsigned& byte, int k) {
    bool pos = zv > 0.0f;
    q = pos ? 1.0f : -1.0f;
    float az = fabsf(zv);
    float d = 1.0f - az;
    commit = fmaf(d, d, commit);
    float a = 4.0f * az;                  // |l0 - l1|
    float e = __expf(-a);                 // in (0,1]
    float r = __fdividef(1.0f, 1.0f + e); // sigmoid(a)
    float ps = e * r;                     // 1 - sigmoid(a)
    ent += fmaf(a, ps, __logf(1.0f + e)); // H(p)
    ch += pos ? r : ps;                   // p0 = sigmoid(4z)
    byte |= (pos ? 1u : 0u) << k;
}

// ---------------- Kernel A: quantize + per-plane partial sums + sign bytes ----
__global__ void __launch_bounds__(THREADS)
lfq_planes(const float* __restrict__ z, float* __restrict__ out) {
    int tid = threadIdx.x;
    int blk = blockIdx.x;
    int p       = blk >> 2;               // plane id = b*13 + c
    int quarter = blk & 3;
    size_t base = (size_t)p * HWSZ + quarter * 4096 + tid * 4;

    float4 v[4];
    #pragma unroll
    for (int i = 0; i < 4; i++)
        v[i] = *reinterpret_cast<const float4*>(z + base + i * 1024);

    float commit = 0.0f, ent = 0.0f, ch = 0.0f;
    int sbase = p * 4096 + quarter * 1024 + tid;
    #pragma unroll
    for (int i = 0; i < 4; i++) {
        float4 q;
        unsigned byte = 0;
        proc(v[i].x, q.x, commit, ent, ch, byte, 0);
        proc(v[i].y, q.y, commit, ent, ch, byte, 1);
        proc(v[i].z, q.z, commit, ent, ch, byte, 2);
        proc(v[i].w, q.w, commit, ent, ch, byte, 3);
        *reinterpret_cast<float4*>(out + base + i * 1024) = q;
        g_signs[sbase + i * 256] = (unsigned char)byte;
    }

    // deterministic block reduction of 3 scalars
    commit = warp_sum(commit);
    ent    = warp_sum(ent);
    ch     = warp_sum(ch);
    __shared__ float sw[3][8];
    int w = tid >> 5;
    if ((tid & 31) == 0) { sw[0][w] = commit; sw[1][w] = ent; sw[2][w] = ch; }
    __syncthreads();
    if (tid == 0) {
        float c0 = 0, e0 = 0, h0 = 0;
        #pragma unroll
        for (int i = 0; i < 8; i++) { c0 += sw[0][i]; e0 += sw[1][i]; h0 += sw[2][i]; }
        *reinterpret_cast<float4*>(&g_partials[blk * 4]) = make_float4(c0, e0, h0, 0.0f);
    }
}

// ---------------- Kernel B: bit-pack indices from sign bytes --------------------
__global__ void __launch_bounds__(THREADS)
lfq_indices(float* __restrict__ out) {
    float* idx_out = out + NTOT + 2;       // 8B-aligned region -> float2 stores
    int g = blockIdx.x * THREADS + threadIdx.x;   // pixel-group id, [0, NPIX/4)
    int b = g >> 12;                       // 4096 groups per batch image
    int local = g & 4095;
    int i0 = 0, i1 = 0, i2 = 0, i3 = 0;
    #pragma unroll
    for (int c = 0; c < CC; c++) {          // MSB = channel 0
        unsigned byte = g_signs[(b * CC + c) * 4096 + local];
        i0 = (i0 << 1) | (byte & 1);
        i1 = (i1 << 1) | ((byte >> 1) & 1);
        i2 = (i2 << 1) | ((byte >> 2) & 1);
        i3 = (i3 << 1) | ((byte >> 3) & 1);
    }
    int pix = g * 4;
    *reinterpret_cast<float2*>(idx_out + pix)     = make_float2((float)i0, (float)i1);
    *reinterpret_cast<float2*>(idx_out + pix + 2) = make_float2((float)i2, (float)i3);
}

// ---------------- Kernel C: deterministic finalize -----------------------------
__global__ void __launch_bounds__(512)
lfq_finalize(float* __restrict__ out) {
    int tid = threadIdx.x;
    int w = tid >> 5, lane = tid & 31;
    __shared__ float sch[CC];
    __shared__ float sce[2][16];

    // commit/ent over all rows, grid-stride (deterministic: fixed assignment)
    float commit = 0.0f, ent = 0.0f;
    for (int r = tid; r < A_BLOCKS; r += 512) {
        commit += g_partials[r * 4 + 0];
        ent    += g_partials[r * 4 + 1];
    }
    commit = warp_sum(commit);
    ent    = warp_sum(ent);
    if (lane == 0) { sce[0][w] = commit; sce[1][w] = ent; }

    // channel sums: warp w (<13) owns channel w; 256 rows per channel
    if (w < CC) {
        float ch = 0.0f;
        // planes p = w + 13k, k=0..63; rows = p*4 + quarter
        for (int k = lane; k < 64; k += 32) {
            int pr = (w + CC * k) * 4;
            #pragma unroll
            for (int qq = 0; qq < 4; qq++) ch += g_partials[(pr + qq) * 4 + 2];
        }
        ch = warp_sum(ch);
        if (lane == 0) sch[w] = ch;
    }
    __syncthreads();

    if (tid == 0) {
        float c0 = 0, e0 = 0;
        #pragma unroll
        for (int i = 0; i < 16; i++) { c0 += sce[0][i]; e0 += sce[1][i]; }
        double commitL = (double)c0 / (double)NTOT * 1.25 * 0.1;
        double entropy = (double)e0 / (double)NTOT;
        double mean_ent = 0.0;
        for (int c = 0; c < CC; c++) {
            double mp = (double)sch[c] / (double)NPIX;
            if (mp < 1e-12) mp = 1e-12;
            if (mp > 1.0 - 1e-12) mp = 1.0 - 1e-12;
            mean_ent += -(mp * log(mp) + (1.0 - mp) * log(1.0 - mp));
        }
        mean_ent /= (double)CC;
        out[NTOT]     = (float)commitL;
        out[NTOT + 1] = (float)((entropy - mean_ent) * 0.1);
    }
}

extern "C" void kernel_launch(void* const* d_in, const int* in_sizes, int n_in,
                              void* d_out, int out_size) {
    const float* z = (const float*)d_in[0];
    float* out = (float*)d_out;
    lfq_planes<<<A_BLOCKS, THREADS>>>(z, out);
    lfq_indices<<<NPIX / 4 / THREADS, THREADS>>>(out);
    lfq_finalize<<<1, 512>>>(out);
}

// round 6
// speedup vs baseline: 3.0842x; 2.1625x over previous
#include <cuda_runtime.h>
#include <cstdint>

// z: (64,13,128,128) fp32
#define BB 64
#define CC 13
#define HWSZ 16384                       // 128*128
#define NPIX (BB*HWSZ)                   // 1,048,576
#define NTOT (CC*NPIX)                   // 13,631,488
#define NPLANES (BB*CC)                  // 832
#define THREADS 256

// Kernel A: each block = one quarter (4096 floats) of one (b,c) plane.
#define A_BLOCKS (NPLANES*4)             // 3328

// Deterministic scratch (fully overwritten every launch; no runtime allocs).
__device__ float g_partials[A_BLOCKS*4];         // [commit, ent, chsum, pad] per block
__device__ unsigned char g_signs[NTOT/4];        // 4 sign bits per byte, 3.4MB

__device__ __forceinline__ float warp_sum(float v) {
    #pragma unroll
    for (int o = 16; o; o >>= 1) v += __shfl_xor_sync(0xffffffffu, v, o);
    return v;
}

__device__ __forceinline__ void proc(float zv, float& q, float& commit,
                                     float& ent, float& ch, unsigned& byte, int k) {
    bool pos = zv > 0.0f;
    q = pos ? 1.0f : -1.0f;
    float az = fabsf(zv);
    float d = 1.0f - az;
    commit = fmaf(d, d, commit);
    float a = 4.0f * az;                  // |l0 - l1|
    float e = __expf(-a);                 // in (0,1]
    float r = __fdividef(1.0f, 1.0f + e); // sigmoid(a)
    float ps = e * r;                     // 1 - sigmoid(a)
    ent += fmaf(a, ps, __logf(1.0f + e)); // H(p)
    ch += pos ? r : ps;                   // p0 = sigmoid(4z)
    byte |= (pos ? 1u : 0u) << k;
}

// ---------------- Kernel A: quantize + per-plane partial sums + sign bytes ----
__global__ void __launch_bounds__(THREADS)
lfq_planes(const float* __restrict__ z, float* __restrict__ out) {
    int tid = threadIdx.x;
    int blk = blockIdx.x;
    int p       = blk >> 2;               // plane id = b*13 + c
    int quarter = blk & 3;
    size_t base = (size_t)p * HWSZ + quarter * 4096 + tid * 4;

    float4 v[4];
    #pragma unroll
    for (int i = 0; i < 4; i++)
        v[i] = *reinterpret_cast<const float4*>(z + base + i * 1024);

    float commit = 0.0f, ent = 0.0f, ch = 0.0f;
    int sbase = p * 4096 + quarter * 1024 + tid;
    #pragma unroll
    for (int i = 0; i < 4; i++) {
        float4 q;
        unsigned byte = 0;
        proc(v[i].x, q.x, commit, ent, ch, byte, 0);
        proc(v[i].y, q.y, commit, ent, ch, byte, 1);
        proc(v[i].z, q.z, commit, ent, ch, byte, 2);
        proc(v[i].w, q.w, commit, ent, ch, byte, 3);
        *reinterpret_cast<float4*>(out + base + i * 1024) = q;
        g_signs[sbase + i * 256] = (unsigned char)byte;
    }

    // deterministic block reduction of 3 scalars
    commit = warp_sum(commit);
    ent    = warp_sum(ent);
    ch     = warp_sum(ch);
    __shared__ float sw[3][8];
    int w = tid >> 5;
    if ((tid & 31) == 0) { sw[0][w] = commit; sw[1][w] = ent; sw[2][w] = ch; }
    __syncthreads();
    if (tid == 0) {
        float c0 = 0, e0 = 0, h0 = 0;
        #pragma unroll
        for (int i = 0; i < 8; i++) { c0 += sw[0][i]; e0 += sw[1][i]; h0 += sw[2][i]; }
        *reinterpret_cast<float4*>(&g_partials[blk * 4]) = make_float4(c0, e0, h0, 0.0f);
    }
}

// -------- Kernel B: blocks 0..511 bit-pack indices; block 512 finalizes --------
__global__ void __launch_bounds__(512)
lfq_pack_finalize(float* __restrict__ out) {
    int tid = threadIdx.x;

    if (blockIdx.x < 512) {
        float* idx_out = out + NTOT + 2;        // 8B-aligned region -> float2 stores
        int g = blockIdx.x * 512 + tid;         // pixel-group id, [0, NPIX/4)
        int b = g >> 12;                        // 4096 groups per batch image
        int local = g & 4095;
        int i0 = 0, i1 = 0, i2 = 0, i3 = 0;
        #pragma unroll
        for (int c = 0; c < CC; c++) {          // MSB = channel 0
            unsigned byte = g_signs[(b * CC + c) * 4096 + local];
            i0 = (i0 << 1) | (byte & 1);
            i1 = (i1 << 1) | ((byte >> 1) & 1);
            i2 = (i2 << 1) | ((byte >> 2) & 1);
            i3 = (i3 << 1) | ((byte >> 3) & 1);
        }
        int pix = g * 4;
        *reinterpret_cast<float2*>(idx_out + pix)     = make_float2((float)i0, (float)i1);
        *reinterpret_cast<float2*>(idx_out + pix + 2) = make_float2((float)i2, (float)i3);
        return;
    }

    // ---------------- finalize block (all fp32, parallel logs) ----------------
    int w = tid >> 5, lane = tid & 31;
    __shared__ float sch[CC];
    __shared__ float sce[2][16];
    __shared__ float sment;

    float commit = 0.0f, ent = 0.0f;
    for (int r = tid; r < A_BLOCKS; r += 512) {
        commit += g_partials[r * 4 + 0];
        ent    += g_partials[r * 4 + 1];
    }
    commit = warp_sum(commit);
    ent    = warp_sum(ent);
    if (lane == 0) { sce[0][w] = commit; sce[1][w] = ent; }

    // channel sums: warp w (<13) owns channel w; 256 rows per channel
    if (w < CC) {
        float chs = 0.0f;
        for (int k = lane; k < 64; k += 32) {       // planes p = w + 13k
            int pr = (w + CC * k) * 4;
            #pragma unroll
            for (int qq = 0; qq < 4; qq++) chs += g_partials[(pr + qq) * 4 + 2];
        }
        chs = warp_sum(chs);
        if (lane == 0) sch[w] = chs;
    }
    __syncthreads();

    // mean-entropy: 13 lanes of warp 0 compute their channel's term in fp32
    if (tid < 32) {
        float me = 0.0f;
        if (tid < CC) {
            float mp = sch[tid] * (1.0f / (float)NPIX);
            mp = fminf(fmaxf(mp, 1e-12f), 1.0f - 1e-7f);
            float mq = 1.0f - mp;
            me = -(mp * __logf(mp) + mq * __logf(mq));
        }
        me = warp_sum(me);
        if (tid == 0) sment = me * (1.0f / (float)CC);
    }
    __syncthreads();

    if (tid == 0) {
        float c0 = 0.0f, e0 = 0.0f;
        #pragma unroll
        for (int i = 0; i < 16; i++) { c0 += sce[0][i]; e0 += sce[1][i]; }
        out[NTOT]     = c0 * (float)(1.25 * 0.1 / (double)NTOT);
        out[NTOT + 1] = (e0 * (float)(1.0 / (double)NTOT) - sment) * 0.1f;
    }
}

extern "C" void kernel_launch(void* const* d_in, const int* in_sizes, int n_in,
                              void* d_out, int out_size) {
    const float* z = (const float*)d_in[0];
    float* out = (float*)d_out;
    lfq_planes<<<A_BLOCKS, THREADS>>>(z, out);
    lfq_pack_finalize<<<513, 512>>>(out);
}

// round 8
// speedup vs baseline: 3.3163x; 1.0753x over previous
#include <cuda_runtime.h>
#include <cstdint>

// z: (64,13,128,128) fp32
#define BB 64
#define CC 13
#define HWSZ 16384                       // 128*128
#define NPIX (BB*HWSZ)                   // 1,048,576
#define NTOT (CC*NPIX)                   // 13,631,488
#define NPLANES (BB*CC)                  // 832
#define THREADS 256

// Kernel A: each block = one quarter (4096 floats) of one (b,c) plane.
#define A_BLOCKS (NPLANES*4)             // 3328

// Deterministic scratch (fully overwritten every launch; no runtime allocs).
__device__ float g_partials[A_BLOCKS*4];          // [commit, ent, chsum, pad] per block
__device__ unsigned int g_signs_w[NTOT/16];       // 4 sign bits/byte (low nibble), word-addressable

__device__ __forceinline__ float warp_sum(float v) {
    #pragma unroll
    for (int o = 16; o; o >>= 1) v += __shfl_xor_sync(0xffffffffu, v, o);
    return v;
}

__device__ __forceinline__ void proc(float zv, float& q, float& commit,
                                     float& ent, float& ch, unsigned& byte, int k) {
    bool pos = zv > 0.0f;
    q = pos ? 1.0f : -1.0f;
    float az = fabsf(zv);
    float d = 1.0f - az;
    commit = fmaf(d, d, commit);
    float a = 4.0f * az;                  // |l0 - l1|
    float e = __expf(-a);                 // in (0,1]
    float r = __fdividef(1.0f, 1.0f + e); // sigmoid(a)
    float ps = e * r;                     // 1 - sigmoid(a)
    ent += fmaf(a, ps, __logf(1.0f + e)); // H(p)
    ch += pos ? r : ps;                   // p0 = sigmoid(4z)
    byte |= (pos ? 1u : 0u) << k;
}

// ---------------- Kernel A: quantize + per-plane partial sums + sign bytes ----
__global__ void __launch_bounds__(THREADS)
lfq_planes(const float* __restrict__ z, float* __restrict__ out) {
    int tid = threadIdx.x;
    int blk = blockIdx.x;
    int p       = blk >> 2;               // plane id = b*13 + c
    int quarter = blk & 3;
    size_t base = (size_t)p * HWSZ + quarter * 4096 + tid * 4;

    float4 v[4];
    #pragma unroll
    for (int i = 0; i < 4; i++)
        v[i] = *reinterpret_cast<const float4*>(z + base + i * 1024);

    unsigned char* g_signs = reinterpret_cast<unsigned char*>(g_signs_w);
    float commit = 0.0f, ent = 0.0f, ch = 0.0f;
    int sbase = p * 4096 + quarter * 1024 + tid;
    #pragma unroll
    for (int i = 0; i < 4; i++) {
        float4 q;
        unsigned byte = 0;
        proc(v[i].x, q.x, commit, ent, ch, byte, 0);
        proc(v[i].y, q.y, commit, ent, ch, byte, 1);
        proc(v[i].z, q.z, commit, ent, ch, byte, 2);
        proc(v[i].w, q.w, commit, ent, ch, byte, 3);
        *reinterpret_cast<float4*>(out + base + i * 1024) = q;
        g_signs[sbase + i * 256] = (unsigned char)byte;   // byte s covers pixels 4s..4s+3
    }

    // deterministic block reduction of 3 scalars
    commit = warp_sum(commit);
    ent    = warp_sum(ent);
    ch     = warp_sum(ch);
    __shared__ float sw[3][8];
    int w = tid >> 5;
    if ((tid & 31) == 0) { sw[0][w] = commit; sw[1][w] = ent; sw[2][w] = ch; }
    __syncthreads();
    if (tid == 0) {
        float c0 = 0, e0 = 0, h0 = 0;
        #pragma unroll
        for (int i = 0; i < 8; i++) { c0 += sw[0][i]; e0 += sw[1][i]; h0 += sw[2][i]; }
        *reinterpret_cast<float4*>(&g_partials[blk * 4]) = make_float4(c0, e0, h0, 0.0f);
    }
}

// -------- Kernel B: blocks 0..127 pack indices (16 px/thread); block 128 finalizes
#define PACK_BLOCKS 128
#define WORDS_PER_PLANE 1024             // 4096 bytes / 4

__global__ void __launch_bounds__(512)
lfq_pack_finalize(float* __restrict__ out) {
    int tid = threadIdx.x;

    if (blockIdx.x < PACK_BLOCKS) {
        float* idx_out = out + NTOT + 2;        // 8B-aligned region -> float2 stores
        int t = blockIdx.x * 512 + tid;         // word id, [0, 65536)
        int b = t >> 10;                        // image
        int wl = t & 1023;                      // word within plane

        // 13 independent coalesced word loads (MLP=13)
        unsigned wv[CC];
        #pragma unroll
        for (int c = 0; c < CC; c++)
            wv[c] = g_signs_w[(b * CC + c) * WORDS_PER_PLANE + wl];

        int pix = (b << 14) + (wl << 4);        // 16 pixels per word
        #pragma unroll
        for (int j = 0; j < 16; j += 2) {
            // pixel j of this word lives at bit 8*(j/4) + (j%4)  (low nibble of byte j/4)
            int bit0 = ((j & 12) << 1) | (j & 3);
            int bit1 = bit0 + 1;                // j even -> j+1 is same byte, next bit
            int i0 = 0, i1 = 0;
            #pragma unroll
            for (int c = 0; c < CC; c++) {      // MSB = channel 0
                i0 = (i0 << 1) | ((wv[c] >> bit0) & 1);
                i1 = (i1 << 1) | ((wv[c] >> bit1) & 1);
            }
            *reinterpret_cast<float2*>(idx_out + pix + j) =
                make_float2((float)i0, (float)i1);
        }
        return;
    }

    // ---------------- finalize block (all fp32, parallel logs) ----------------
    int w = tid >> 5, lane = tid & 31;
    __shared__ float sch[CC];
    __shared__ float sce[2][16];
    __shared__ float sment;

    float commit = 0.0f, ent = 0.0f;
    for (int r = tid; r < A_BLOCKS; r += 512) {
        commit += g_partials[r * 4 + 0];
        ent    += g_partials[r * 4 + 1];
    }
    commit = warp_sum(commit);
    ent    = warp_sum(ent);
    if (lane == 0) { sce[0][w] = commit; sce[1][w] = ent; }

    // channel sums: warp w (<13) owns channel w; 256 rows per channel
    if (w < CC) {
        float chs = 0.0f;
        for (int k = lane; k < 64; k += 32) {       // planes p = w + 13k
            int pr = (w + CC * k) * 4;
            #pragma unroll
            for (int qq = 0; qq < 4; qq++) chs += g_partials[(pr + qq) * 4 + 2];
        }
        chs = warp_sum(chs);
        if (lane == 0) sch[w] = chs;
    }
    __syncthreads();

    // mean-entropy: 13 lanes of warp 0 compute their channel's term in fp32
    if (tid < 32) {
        float me = 0.0f;
        if (tid < CC) {
            float mp = sch[tid] * (1.0f / (float)NPIX);
            mp = fminf(fmaxf(mp, 1e-12f), 1.0f - 1e-7f);
            float mq = 1.0f - mp;
            me = -(mp * __logf(mp) + mq * __logf(mq));
        }
        me = warp_sum(me);
        if (tid == 0) sment = me * (1.0f / (float)CC);
    }
    __syncthreads();

    if (tid == 0) {
        float c0 = 0.0f, e0 = 0.0f;
        #pragma unroll
        for (int i = 0; i < 16; i++) { c0 += sce[0][i]; e0 += sce[1][i]; }
        out[NTOT]     = c0 * (float)(1.25 * 0.1 / (double)NTOT);
        out[NTOT + 1] = (e0 * (float)(1.0 / (double)NTOT) - sment) * 0.1f;
    }
}

extern "C" void kernel_launch(void* const* d_in, const int* in_sizes, int n_in,
                              void* d_out, int out_size) {
    const float* z = (const float*)d_in[0];
    float* out = (float*)d_out;
    lfq_planes<<<A_BLOCKS, THREADS>>>(z, out);
    lfq_pack_finalize<<<PACK_BLOCKS + 1, 512>>>(out);
}